// round 14
// baseline (speedup 1.0000x reference)
#include <cuda_runtime.h>
#include <math.h>
#include <stdint.h>
#include <stddef.h>

#define BB 16
#define CC 200
#define TCI 1000
#define TT 6000
#define HH 200
#define G4 800
#define HIDN 100
#define ROWS (TT*BB)   // 96000

// ---------------- device scratch (no runtime allocations allowed) ----------------
__device__ float g_wt[30 * CC * CC];                    // conv weights [k][ci][co]
__device__ float g_yact[(size_t)BB * CC * TT];          // GELU(convT) [b][c][t]
__device__ float g_xin[(size_t)ROWS * CC];              // lstm1 inputs [t*B+b][c]
__device__ float g_zbuf[(size_t)ROWS * G4];             // gate pre-acts [t*B+b][800]
__device__ float g_h1[(size_t)(TT + 1) * BB * HH];      // layer1 h, rows 0..6000
__device__ float g_h2[(size_t)(TT + 1) * BB * HH];      // layer2 h
__device__ float g_hid[(size_t)ROWS * HIDN];            // mlp hidden
__device__ float g_tmp[(size_t)ROWS * CC];              // mlp out [t*B+b][f]
__device__ float g_a[CC], g_d[CC];                      // BN fold: x_hat = a*y + d
__device__ unsigned g_ctr[32];                          // per-batch step counters

// ---------------- helpers ----------------
__device__ __forceinline__ unsigned ld_acquire(const unsigned* p) {
    unsigned v;
    asm volatile("ld.acquire.gpu.global.u32 %0, [%1];" : "=r"(v) : "l"(p) : "memory");
    return v;
}
__device__ __forceinline__ float sigf(float x) {
    return 1.f / (1.f + expf(-x));
}

// ---------------- prep: zero counters ----------------
__global__ void k_prep() {
    if (threadIdx.x < 32) g_ctr[threadIdx.x] = 0;
}

// ---------------- conv weight transpose [ci][co][k] -> [k][ci][co] ----------------
__global__ void k_wt(const float* __restrict__ conv_w) {
    int e = blockIdx.x * 256 + threadIdx.x;
    if (e >= 30 * CC * CC) return;
    int k = e / (CC * CC);
    int rem = e % (CC * CC);
    int ci = rem / CC, co = rem % CC;
    g_wt[e] = conv_w[(ci * CC + co) * 30 + k];
}

// ---------------- ConvTranspose1d (K=30, s=6, p=12) + exact GELU ----------------
// y[b,co,t] = bias[co] + sum_{ci,k : t = 6*tc - 12 + k} x[b,ci,tc] * w[ci,co,k]
// t-tile of 60 per block (s = 0..9), 256 threads, co = tid (<200 active).
__global__ void k_conv(const float* __restrict__ x, const float* __restrict__ conv_b) {
    __shared__ float xs[CC][14];
    int t0 = blockIdx.x * 60;
    int b = blockIdx.y;
    int tcbase = t0 / 6 - 2;
    int tid = threadIdx.x;
    for (int idx = tid; idx < CC * 14; idx += 256) {
        int ci = idx / 14, q = idx % 14;
        int tc = tcbase + q;
        xs[ci][q] = (tc >= 0 && tc < TCI) ? x[(size_t)(b * CC + ci) * TCI + tc] : 0.f;
    }
    __syncthreads();
    int co = tid;
    if (co >= CC) return;
    float acc[60];
    float bias = conv_b[co];
#pragma unroll
    for (int i = 0; i < 60; i++) acc[i] = bias;
    for (int ci = 0; ci < CC; ci++) {
        float xr[14];
#pragma unroll
        for (int q = 0; q < 14; q++) xr[q] = xs[ci][q];
        const float* wp = g_wt + ci * CC + co;
#pragma unroll
        for (int k = 0; k < 30; k++) {
            float wv = wp[(size_t)k * CC * CC];
            int kd = k / 6, km = k % 6;
#pragma unroll
            for (int s = 0; s < 10; s++)
                acc[km + 6 * s] = fmaf(wv, xr[4 + s - kd], acc[km + 6 * s]);
        }
    }
    float* yp = g_yact + ((size_t)(b * CC + co)) * TT + t0;
#pragma unroll
    for (int i = 0; i < 60; i++) {
        float v = acc[i];
        yp[i] = 0.5f * v * (1.f + erff(v * 0.70710678118654752f));
    }
}

// ---------------- per-channel BN stats -> fold into (a, d) ----------------
__global__ void k_stats(const float* __restrict__ bn_g, const float* __restrict__ bn_b) {
    __shared__ float rs[256], rq[256];
    int c = blockIdx.x;
    int tid = threadIdx.x;
    float s = 0.f, q = 0.f;
    for (int b = 0; b < BB; b++) {
        const float* p = g_yact + (size_t)(b * CC + c) * TT;
        for (int t = tid; t < TT; t += 256) {
            float v = p[t];
            s += v; q += v * v;
        }
    }
    rs[tid] = s; rq[tid] = q;
    __syncthreads();
    for (int st = 128; st > 0; st >>= 1) {
        if (tid < st) { rs[tid] += rs[tid + st]; rq[tid] += rq[tid + st]; }
        __syncthreads();
    }
    if (tid == 0) {
        float inv = 1.f / (float)(BB * TT);
        float mu = rs[0] * inv;
        float var = rq[0] * inv - mu * mu;
        float a = bn_g[c] * rsqrtf(var + 1e-5f);
        g_a[c] = a;
        g_d[c] = bn_b[c] - mu * a;
    }
}

// ---------------- build LSTM-1 input matrix X[t*B+b][c] (tiled transpose) ----------
// row t=0: x_meg[b,c,0]; row t>0: a[c]*y[b,c,t-1] + d[c]
__global__ void k_xin(const float* __restrict__ x_meg) {
    __shared__ float tl[32][33];
    int t0 = blockIdx.x * 32, c0 = blockIdx.y * 32, b = blockIdx.z;
    int tx = threadIdx.x, ty = threadIdx.y;  // 32 x 8
    for (int yy = ty; yy < 32; yy += 8) {
        int c = c0 + yy, t = t0 + tx;
        float v = 0.f;
        if (c < CC && t < TT) {
            if (t == 0)
                v = x_meg[(size_t)(b * CC + c) * TT];
            else
                v = g_a[c] * g_yact[(size_t)(b * CC + c) * TT + (t - 1)] + g_d[c];
        }
        tl[yy][tx] = v;
    }
    __syncthreads();
    for (int yy = ty; yy < 32; yy += 8) {
        int t = t0 + yy, c = c0 + tx;
        if (t < TT && c < CC)
            g_xin[((size_t)t * BB + b) * CC + c] = tl[tx][yy];
    }
}

// ---------------- tiled SGEMM-TN: C[M,N] = A[M,K] * B[N,K]^T + bias1(+bias2) ------
// mode: 1 z1 (A=g_xin,  C=g_zbuf), 2 z2 (A=g_h1+3200, C=g_zbuf),
//       3 hid(A=g_h2+3200, C=g_hid, ReLU), 4 out (A=g_hid, C=g_tmp)
// bias1/bias2 are HARNESS device pointers (never __device__ symbols!).
__global__ __launch_bounds__(256) void k_gemm(int mode, const float* __restrict__ B,
                                              const float* __restrict__ bias1,
                                              const float* __restrict__ bias2,
                                              int N, int K) {
    const float* A;
    float* C;
    bool relu = false;
    if (mode == 1)      { A = g_xin;        C = g_zbuf; }
    else if (mode == 2) { A = g_h1 + BB*HH; C = g_zbuf; }
    else if (mode == 3) { A = g_h2 + BB*HH; C = g_hid;  relu = true; }
    else                { A = g_hid;        C = g_tmp;  }

    __shared__ float As[8][132];
    __shared__ float Bs[8][68];
    int m0 = blockIdx.x * 128, n0 = blockIdx.y * 64;
    int tid = threadIdx.x;
    int tx = tid & 15, ty = tid >> 4;
    float acc[8][4];
#pragma unroll
    for (int u = 0; u < 8; u++)
#pragma unroll
        for (int v = 0; v < 4; v++) acc[u][v] = 0.f;

    for (int k0 = 0; k0 < K; k0 += 8) {
#pragma unroll
        for (int r = 0; r < 4; r++) {
            int idx = tid + r * 256;
            int i = idx >> 3, j = idx & 7;
            int kk = k0 + j;
            As[j][i] = (kk < K) ? A[(size_t)(m0 + i) * K + kk] : 0.f;
        }
#pragma unroll
        for (int r = 0; r < 2; r++) {
            int idx = tid + r * 256;
            int i = idx >> 3, j = idx & 7;
            int kk = k0 + j;
            Bs[j][i] = (n0 + i < N && kk < K) ? B[(size_t)(n0 + i) * K + kk] : 0.f;
        }
        __syncthreads();
#pragma unroll
        for (int kk = 0; kk < 8; kk++) {
            float a[8], bv[4];
#pragma unroll
            for (int u = 0; u < 8; u++) a[u] = As[kk][ty * 8 + u];
#pragma unroll
            for (int v = 0; v < 4; v++) bv[v] = Bs[kk][tx * 4 + v];
#pragma unroll
            for (int u = 0; u < 8; u++)
#pragma unroll
                for (int v = 0; v < 4; v++)
                    acc[u][v] = fmaf(a[u], bv[v], acc[u][v]);
        }
        __syncthreads();
    }
#pragma unroll
    for (int v = 0; v < 4; v++) {
        int n = n0 + tx * 4 + v;
        if (n >= N) continue;
        float bb = bias1[n] + (bias2 ? bias2[n] : 0.f);
#pragma unroll
        for (int u = 0; u < 8; u++) {
            int m = m0 + ty * 8 + u;
            float val = acc[u][v] + bb;
            if (relu) val = fmaxf(val, 0.f);
            C[(size_t)m * N + n] = val;
        }
    }
}

// ---------------- sequential LSTM sweep (one layer) ----------------
// 128 blocks: b = blk/8, slice bs = blk%8 owns hidden units [bs*25, bs*25+25).
// 256 threads: gl = tid/2 (gate_local < 100 = 4 gate types x 25 units),
// kh = tid&1 (k half of 100). W_hh slice in registers (100/thread).
__global__ __launch_bounds__(256, 1) void k_sweep(const float* __restrict__ whh,
                                                  const float* __restrict__ h0l,
                                                  const float* __restrict__ c0l,
                                                  int layer) {
    __shared__ float h_s[HH];
    __shared__ float c_s[25];
    __shared__ float gbuf[100];
    float* hout = layer ? g_h2 : g_h1;
    int ctrbase = layer * 16;

    int tid = threadIdx.x;
    int b = blockIdx.x >> 3, bs = blockIdx.x & 7;
    int gl = tid >> 1, kh = tid & 1;
    bool act = (gl < 100);

    float w[100];
    if (act) {
        int gt = gl / 25, jl = gl % 25;
        const float* wp = whh + (size_t)(gt * 200 + bs * 25 + jl) * HH + kh * 100;
#pragma unroll
        for (int j = 0; j < 100; j++) w[j] = wp[j];
    } else {
#pragma unroll
        for (int j = 0; j < 100; j++) w[j] = 0.f;
    }
    if (tid < HH) h_s[tid] = h0l[tid];
    if (tid < 25) c_s[tid] = c0l[bs * 25 + tid];
    __syncthreads();

    unsigned* ctr = &g_ctr[ctrbase + b];
    float z0 = 0.f, z1 = 0.f, z2 = 0.f, z3 = 0.f;
    if (tid < 25) {
        const float* zr = g_zbuf + (size_t)b * G4 + bs * 25 + tid;  // row r = 0*16+b
        z0 = zr[0]; z1 = zr[200]; z2 = zr[400]; z3 = zr[600];
    }

    for (int t = 0; t < TT; t++) {
        // gate dot: h_t . w_hh_row (two k-halves, 4 partial accumulators)
        const float* hb = h_s + kh * 100;
        float p0 = 0.f, p1 = 0.f, p2 = 0.f, p3 = 0.f;
#pragma unroll
        for (int j = 0; j < 100; j += 4) {
            p0 = fmaf(w[j + 0], hb[j + 0], p0);
            p1 = fmaf(w[j + 1], hb[j + 1], p1);
            p2 = fmaf(w[j + 2], hb[j + 2], p2);
            p3 = fmaf(w[j + 3], hb[j + 3], p3);
        }
        float p = (p0 + p1) + (p2 + p3);
        p += __shfl_xor_sync(0xffffffffu, p, 1);
        if (!kh && act) gbuf[gl] = p;
        __syncthreads();

        if (tid < 25) {
            float zi = z0 + gbuf[tid];
            float zf = z1 + gbuf[25 + tid];
            float zg = z2 + gbuf[50 + tid];
            float zo = z3 + gbuf[75 + tid];
            float c = sigf(zf) * c_s[tid] + sigf(zi) * tanhf(zg);
            c_s[tid] = c;
            float h = sigf(zo) * tanhf(c);
            hout[(size_t)(t + 1) * (BB * HH) + b * HH + bs * 25 + tid] = h;
        }
        __syncthreads();

        if (tid == 0) {
            __threadfence();
            atomicAdd(ctr, 1u);
        }
        // prefetch next z row while waiting
        if (t + 1 < TT && tid < 25) {
            const float* zr = g_zbuf + ((size_t)(t + 1) * BB + b) * G4 + bs * 25 + tid;
            z0 = zr[0]; z1 = zr[200]; z2 = zr[400]; z3 = zr[600];
        }
        if (tid == 0) {
            unsigned tgt = 8u * (unsigned)(t + 1);
            while (ld_acquire(ctr) < tgt) {}
        }
        __syncthreads();
        if (tid < HH)
            h_s[tid] = hout[(size_t)(t + 1) * (BB * HH) + b * HH + tid];
        __syncthreads();
    }
}

// ---------------- final transpose: g_tmp[t*B+b][f] -> d_out[b][f][t] ----------------
__global__ void k_tr(float* __restrict__ out) {
    __shared__ float tl[32][33];
    int t0 = blockIdx.x * 32, f0 = blockIdx.y * 32, b = blockIdx.z;
    int tx = threadIdx.x, ty = threadIdx.y;  // 32 x 8
    for (int yy = ty; yy < 32; yy += 8) {
        int t = t0 + yy, f = f0 + tx;
        tl[yy][tx] = (t < TT && f < CC) ? g_tmp[((size_t)t * BB + b) * CC + f] : 0.f;
    }
    __syncthreads();
    for (int yy = ty; yy < 32; yy += 8) {
        int f = f0 + yy, t = t0 + tx;
        if (t < TT && f < CC)
            out[(size_t)(b * CC + f) * TT + t] = tl[tx][yy];
    }
}

// ---------------- host launcher ----------------
extern "C" void kernel_launch(void* const* d_in, const int* in_sizes, int n_in,
                              void* d_out, int out_size) {
    const float* x_fmri = (const float*)d_in[0];
    const float* x_meg  = (const float*)d_in[1];
    const float* conv_w = (const float*)d_in[2];
    const float* conv_b = (const float*)d_in[3];
    const float* bn_g   = (const float*)d_in[4];
    const float* bn_b   = (const float*)d_in[5];
    const float* w_ih0  = (const float*)d_in[6];
    const float* w_hh0  = (const float*)d_in[7];
    const float* b_ih0  = (const float*)d_in[8];
    const float* b_hh0  = (const float*)d_in[9];
    const float* w_ih1  = (const float*)d_in[10];
    const float* w_hh1  = (const float*)d_in[11];
    const float* b_ih1  = (const float*)d_in[12];
    const float* b_hh1  = (const float*)d_in[13];
    const float* out1_w = (const float*)d_in[14];
    const float* out1_b = (const float*)d_in[15];
    const float* out2_w = (const float*)d_in[16];
    const float* out2_b = (const float*)d_in[17];
    const float* h0     = (const float*)d_in[18];
    const float* c0     = (const float*)d_in[19];
    float* out = (float*)d_out;

    k_prep<<<1, 32>>>();
    k_wt<<<(30 * CC * CC + 255) / 256, 256>>>(conv_w);
    k_conv<<<dim3(TT / 60, BB), 256>>>(x_fmri, conv_b);
    k_stats<<<CC, 256>>>(bn_g, bn_b);
    k_xin<<<dim3(188, 7, BB), dim3(32, 8)>>>(x_meg);

    // z1 = X @ w_ih0^T + b_ih0 + b_hh0
    k_gemm<<<dim3(ROWS / 128, (G4 + 63) / 64), 256>>>(1, w_ih0, b_ih0, b_hh0, G4, CC);
    // layer-1 sweep
    k_sweep<<<128, 256>>>(w_hh0, h0, c0, 0);
    // z2 = H1 @ w_ih1^T + b_ih1 + b_hh1
    k_gemm<<<dim3(ROWS / 128, (G4 + 63) / 64), 256>>>(2, w_ih1, b_ih1, b_hh1, G4, HH);
    // layer-2 sweep
    k_sweep<<<128, 256>>>(w_hh1, h0 + HH, c0 + HH, 1);
    // hid = relu(H2 @ out1_w^T + out1_b)
    k_gemm<<<dim3(ROWS / 128, (HIDN + 63) / 64), 256>>>(3, out1_w, out1_b, nullptr, HIDN, HH);
    // out = hid @ out2_w^T + out2_b
    k_gemm<<<dim3(ROWS / 128, (CC + 63) / 64), 256>>>(4, out2_w, out2_b, nullptr, CC, HIDN);
    // transpose to [b][f][t]
    k_tr<<<dim3(188, 7, BB), dim3(32, 8)>>>(out);
}